// round 14
// baseline (speedup 1.0000x reference)
#include <cuda_runtime.h>
#include <cuda_fp16.h>
#include <cstdint>

// ---------------------------------------------------------------------------
// y[m, n*410+f] = u[m,f] + sx[m,n]*G[n,f] + c[f]
// FUSED: one fp16 GEMM kernel computes u (104 fc cols/block) AND sx (10 sel
// cols, redundantly per block) and writes out directly. No U scratch, no epi.
//   G = Wfc @ Wexp, c = Wfc @ bexp + bfc  (prep)
// GEMM: mma.sync m16n8k16 fp16, BM=128/BN=128/BK=64, 128 thr, 4 warps of
// 32x128 (r12's validated 1-warp/SMSP regime), cp.async 4-stage ring.
// Block bx column map: j<104 -> Wfc row bx*104+j (pad if >=410),
//                      j in [104,114) -> Wsel row j-104, else zero pad.
// ---------------------------------------------------------------------------

#define KDIM    4096
#define NFC     410
#define NCOLS   420
#define NBT     448
#define MMAX    4096

#define BM 128
#define BN 128
#define BK 64                        // fp16 elems -> 128 bytes per smem row
#define NKT (KDIM / BK)              // 64
#define STAGES 4
#define TILE_A  (BM * BK * 2)        // 16384
#define TILE_B  (BN * BK * 2)        // 16384
#define STAGE_BYTES (TILE_A + TILE_B) // 32768

#define KSPLIT 8
#define PREPW  4576

__device__ float  g_G[10 * 416];
__device__ float  g_c[416];
__device__ float  g_part[KSPLIT][PREPW];
__device__ __half g_Bt[NBT * KDIM];    // fp16 B (Wfc | Wsel | 0-pad)
__device__ __half g_xh[MMAX * KDIM];   // fp16 X

// ---------------- helpers ----------------------------------------------------
__device__ __forceinline__ uint32_t smem_u32(const void* p) {
    uint32_t a;
    asm("{ .reg .u64 t; cvta.to.shared.u64 t, %1; cvt.u32.u64 %0, t; }" : "=r"(a) : "l"(p));
    return a;
}
__device__ __forceinline__ void cp16(uint32_t dst, const void* src) {
    asm volatile("cp.async.cg.shared.global [%0], [%1], 16;"
                 :: "r"(dst), "l"(src) : "memory");
}
__device__ __forceinline__ void cp_commit() {
    asm volatile("cp.async.commit_group;" ::: "memory");
}
__device__ __forceinline__ void cp_wait2() {
    asm volatile("cp.async.wait_group 2;" ::: "memory");
}
__device__ __forceinline__ void ldsm4(uint32_t* r, uint32_t a) {
    asm volatile("ldmatrix.sync.aligned.m8n8.x4.shared.b16 {%0,%1,%2,%3}, [%4];"
                 : "=r"(r[0]), "=r"(r[1]), "=r"(r[2]), "=r"(r[3]) : "r"(a));
}
__device__ __forceinline__ void mma16(float* c, const uint32_t* a, const uint32_t* b) {
    asm volatile(
        "mma.sync.aligned.m16n8k16.row.col.f32.f16.f16.f32 "
        "{%0,%1,%2,%3}, {%4,%5,%6,%7}, {%8,%9}, {%0,%1,%2,%3};"
        : "+f"(c[0]), "+f"(c[1]), "+f"(c[2]), "+f"(c[3])
        : "r"(a[0]), "r"(a[1]), "r"(a[2]), "r"(a[3]), "r"(b[0]), "r"(b[1]));
}

// ---------------------------------------------------------------------------
// x -> fp16 (8 elems/thread, vectorized)
// ---------------------------------------------------------------------------
__global__ void xh_kernel(const float* __restrict__ x) {
    int i = (blockIdx.x * 256 + threadIdx.x) * 8;
    float4 v0 = *reinterpret_cast<const float4*>(x + i);
    float4 v1 = *reinterpret_cast<const float4*>(x + i + 4);
    __half2 h0 = __floats2half2_rn(v0.x, v0.y);
    __half2 h1 = __floats2half2_rn(v0.z, v0.w);
    __half2 h2 = __floats2half2_rn(v1.x, v1.y);
    __half2 h3 = __floats2half2_rn(v1.z, v1.w);
    uint4 pk;
    pk.x = *reinterpret_cast<uint32_t*>(&h0);
    pk.y = *reinterpret_cast<uint32_t*>(&h1);
    pk.z = *reinterpret_cast<uint32_t*>(&h2);
    pk.w = *reinterpret_cast<uint32_t*>(&h3);
    *reinterpret_cast<uint4*>(g_xh + i) = pk;
}

// ---------------------------------------------------------------------------
// prep pass 1: G/c partials (f<410) + fp16 B materialization (all f<448)
// ---------------------------------------------------------------------------
__global__ void prep_part(const float* __restrict__ Wfc, const float* __restrict__ Wsel,
                          const float* __restrict__ Wexp, const float* __restrict__ bexp) {
    int f  = blockIdx.x;                 // 0..447
    int kz = blockIdx.y;
    int k0 = kz * 512;
    const float* src = nullptr;
    if (f < NFC)        src = Wfc + (size_t)f * KDIM + k0;
    else if (f < NCOLS) src = Wsel + (size_t)(f - NFC) * KDIM + k0;

    float acc[11];
#pragma unroll
    for (int v = 0; v < 11; v++) acc[v] = 0.f;

#pragma unroll
    for (int it = 0; it < 4; it++) {
        int k = it * 128 + threadIdx.x;
        float w = src ? src[k] : 0.f;
        g_Bt[(size_t)f * KDIM + k0 + k] = __float2half_rn(w);
        if (f < NFC) {
            const float* we = Wexp + (size_t)(k0 + k) * 10;
#pragma unroll
            for (int n = 0; n < 10; n++) acc[n] += w * we[n];
            acc[10] += w * bexp[k0 + k];
        }
    }
    if (f >= NFC) return;

    __shared__ float red[4][11];
    int lane = threadIdx.x & 31, warp = threadIdx.x >> 5;
#pragma unroll
    for (int v = 0; v < 11; v++) {
        float s = acc[v];
#pragma unroll
        for (int o = 16; o; o >>= 1) s += __shfl_xor_sync(0xffffffffu, s, o);
        if (lane == 0) red[warp][v] = s;
    }
    __syncthreads();
    if (threadIdx.x < 11) {
        float s = red[0][threadIdx.x] + red[1][threadIdx.x] +
                  red[2][threadIdx.x] + red[3][threadIdx.x];
        g_part[kz][threadIdx.x * 416 + f] = s;
    }
}

__global__ void prep_combine(const float* __restrict__ bfc) {
    int i = blockIdx.x * 256 + threadIdx.x;
    if (i >= PREPW) return;
    float s = 0.f;
#pragma unroll
    for (int kz = 0; kz < KSPLIT; kz++) s += g_part[kz][i];
    if (i < 10 * 416) {
        g_G[i] = s;
    } else {
        int f = i - 10 * 416;
        g_c[f] = (f < NFC) ? s + bfc[f] : s;
    }
}

// ---------------------------------------------------------------------------
// fused GEMM + epilogue: 128x128 block, 128 thr, 4 warps of 32x128
// ---------------------------------------------------------------------------
__global__ __launch_bounds__(128, 1)
void gemm_kernel(const float* __restrict__ bsel, float* __restrict__ out) {
    extern __shared__ char dyn[];
    char* bufs = (char*)(((uintptr_t)dyn + 1023) & ~(uintptr_t)1023);
    const uint32_t bufs_u32 = smem_u32(bufs);

    const int tid  = threadIdx.x;
    const int lane = tid & 31;
    const int warp = tid >> 5;         // wm 0..3 (rows), full 128 cols per warp
    const int m0   = blockIdx.y * BM;
    const int off_b = blockIdx.x * 104;   // fc column offset of this block

    // ---- loaders: lrow 0..15 (+16i slabs), 16B chunk lq ----
    const int lrow = tid >> 3;
    const int lq   = tid & 7;
    const uint32_t dstoff = (uint32_t)(lrow * 128 + ((lq * 16) ^ ((lrow & 7) << 4)));
    const char* aglob = (const char*)(g_xh + (size_t)(m0 + lrow) * KDIM) + lq * 16;

    // B row map: j<104 -> fc (pad if >=410); j in [104,114) -> sel; else pad
    const char* bptr[8];
#pragma unroll
    for (int i = 0; i < 8; i++) {
        int j = i * 16 + lrow;
        int q;
        if (j < 104) {
            q = off_b + j;
            if (q >= NFC) q = 424 + (q - NFC);      // zero pad rows
        } else if (j < 114) {
            q = NFC + (j - 104);                     // Wsel rows
        } else {
            q = 432 + (j - 114);                     // zero pad rows
        }
        bptr[i] = (const char*)(g_Bt + (size_t)q * KDIM) + lq * 16;
    }

    auto issue = [&](int kt) {
        int stage = kt & (STAGES - 1);
        uint32_t ad = bufs_u32 + stage * STAGE_BYTES + dstoff;
        uint32_t bd = ad + TILE_A;
        const char* as = aglob + (size_t)kt * 128;
#pragma unroll
        for (int i = 0; i < 8; i++)
            cp16(ad + i * 2048, as + (size_t)i * (16 * KDIM * 2));
#pragma unroll
        for (int i = 0; i < 8; i++)
            cp16(bd + i * 2048, bptr[i] + (size_t)kt * 128);
    };

    // ---- fragment constants (validated byte addressing) ----
    const uint32_t aoff = (uint32_t)((warp * 32 + (lane & 15)) * 128);
    const uint32_t xS   = (uint32_t)((lane & 7) << 4);
    const uint32_t hA   = (lane & 16) ? 16u : 0u;
    const uint32_t boff = (uint32_t)(((lane & 7) + ((lane & 16) ? 8 : 0)) * 128);
    const uint32_t hB   = (lane & 8) ? 16u : 0u;

    float acc[2][16][4];
#pragma unroll
    for (int mi = 0; mi < 2; mi++)
#pragma unroll
        for (int nj = 0; nj < 16; nj++)
#pragma unroll
            for (int q = 0; q < 4; q++) acc[mi][nj][q] = 0.f;

    issue(0); cp_commit();
    issue(1); cp_commit();
    issue(2); cp_commit();

#pragma unroll 1
    for (int kt = 0; kt < NKT; kt++) {
        cp_wait2();
        __syncthreads();
        if (kt + 3 < NKT) issue(kt + 3);
        cp_commit();

        const uint32_t As = bufs_u32 + (kt & (STAGES - 1)) * STAGE_BYTES;
        const uint32_t Bs = As + TILE_A;
#pragma unroll
        for (int ks = 0; ks < 4; ks++) {
            const uint32_t ka = (uint32_t)(ks * 32 + hA) ^ xS;
            const uint32_t kb = (uint32_t)(ks * 32 + hB) ^ xS;
            uint32_t a[2][4], b[8][4];
#pragma unroll
            for (int mi = 0; mi < 2; mi++) ldsm4(a[mi], As + aoff + mi * 2048 + ka);
#pragma unroll
            for (int p = 0; p < 8; p++)   ldsm4(b[p], Bs + boff + p * 2048 + kb);
#pragma unroll
            for (int mi = 0; mi < 2; mi++)
#pragma unroll
                for (int p = 0; p < 8; p++) {
                    mma16(acc[mi][2 * p],     a[mi], &b[p][0]);
                    mma16(acc[mi][2 * p + 1], a[mi], &b[p][2]);
                }
        }
    }

    // ================= fused epilogue =================
    const int gid = lane >> 2;
    const int tig = lane & 3;
    __syncthreads();                 // mainloop smem dead; reuse buffers

    float* sxbuf = reinterpret_cast<float*>(bufs);        // [128][12]
    float* Gs    = sxbuf + 128 * 12;                      // [10][104]
    float* cs    = Gs + 10 * 104;                         // [104]

    // write sx (sel cols 104..113 = nj 13 pair + nj 14 first pair) + bsel
#pragma unroll
    for (int mi = 0; mi < 2; mi++) {
        int r0 = warp * 32 + mi * 16 + gid;
        sxbuf[r0 * 12 + 2 * tig]           = acc[mi][13][0] + bsel[2 * tig];
        sxbuf[r0 * 12 + 2 * tig + 1]       = acc[mi][13][1] + bsel[2 * tig + 1];
        sxbuf[(r0 + 8) * 12 + 2 * tig]     = acc[mi][13][2] + bsel[2 * tig];
        sxbuf[(r0 + 8) * 12 + 2 * tig + 1] = acc[mi][13][3] + bsel[2 * tig + 1];
        if (tig == 0) {
            sxbuf[r0 * 12 + 8]       = acc[mi][14][0] + bsel[8];
            sxbuf[r0 * 12 + 9]       = acc[mi][14][1] + bsel[9];
            sxbuf[(r0 + 8) * 12 + 8] = acc[mi][14][2] + bsel[8];
            sxbuf[(r0 + 8) * 12 + 9] = acc[mi][14][3] + bsel[9];
        }
    }
    // stage G/c slab
#pragma unroll 1
    for (int n = 0; n < 10; n++)
        for (int j = tid; j < 104; j += 128) Gs[n * 104 + j] = g_G[n * 416 + off_b + j];
    for (int j = tid; j < 104; j += 128) cs[j] = g_c[off_b + j];
    __syncthreads();

    // stores: fc cols are nj 0..12 (col = nj*8 + 2*tig < 104)
#pragma unroll 1
    for (int nj = 0; nj < 13; nj++) {
        int col = nj * 8 + 2 * tig;
        int f = off_b + col;
        if (f >= NFC) continue;                    // block-3 pad tail
        float2 c2 = *reinterpret_cast<float2*>(cs + col);
        float2 g2[10];
#pragma unroll
        for (int n = 0; n < 10; n++)
            g2[n] = *reinterpret_cast<float2*>(Gs + n * 104 + col);
#pragma unroll
        for (int mi = 0; mi < 2; mi++) {
            int r0 = warp * 32 + mi * 16 + gid;
            float* o0 = out + (size_t)(m0 + r0) * 4096;
            float* o1 = out + (size_t)(m0 + r0 + 8) * 4096;
            float u0x = acc[mi][nj][0] + c2.x, u0y = acc[mi][nj][1] + c2.y;
            float u1x = acc[mi][nj][2] + c2.x, u1y = acc[mi][nj][3] + c2.y;
#pragma unroll
            for (int n = 0; n < 10; n++) {
                if (n == 9 && f >= 406) break;     // out truncated at 4096
                float s0 = sxbuf[r0 * 12 + n];
                float s1 = sxbuf[(r0 + 8) * 12 + n];
                float2 v0 = make_float2(fmaf(s0, g2[n].x, u0x), fmaf(s0, g2[n].y, u0y));
                float2 v1 = make_float2(fmaf(s1, g2[n].x, u1x), fmaf(s1, g2[n].y, u1y));
                *reinterpret_cast<float2*>(o0 + n * NFC + f) = v0;
                *reinterpret_cast<float2*>(o1 + n * NFC + f) = v1;
            }
        }
    }
}

// ---------------------------------------------------------------------------
extern "C" void kernel_launch(void* const* d_in, const int* in_sizes, int n_in,
                              void* d_out, int out_size) {
    const float* x    = (const float*)d_in[0];
    const float* Wsel = (const float*)d_in[1];
    const float* bsel = (const float*)d_in[2];
    const float* Wexp = (const float*)d_in[3];
    const float* bexp = (const float*)d_in[4];
    const float* Wfc  = (const float*)d_in[5];
    const float* bfc  = (const float*)d_in[6];
    float* out = (float*)d_out;

    int M = in_sizes[0] / KDIM;   // 4096

    const int smem_bytes = STAGES * STAGE_BYTES + 1024;   // 132096
    cudaFuncSetAttribute(gemm_kernel, cudaFuncAttributeMaxDynamicSharedMemorySize, smem_bytes);

    xh_kernel<<<(M * KDIM) / (256 * 8), 256>>>(x);
    prep_part<<<dim3(NBT, KSPLIT), 128>>>(Wfc, Wsel, Wexp, bexp);
    prep_combine<<<(PREPW + 255) / 256, 256>>>(bfc);
    dim3 grid(4, M / BM);   // 4 x 32 = 128 blocks
    gemm_kernel<<<grid, 128, smem_bytes>>>(bsel, out);
}

// round 15
// speedup vs baseline: 2.8473x; 2.8473x over previous
#include <cuda_runtime.h>
#include <cuda_fp16.h>
#include <cstdint>

// ---------------------------------------------------------------------------
// y[m, n*410+f] = u[m,f] + sx[m,n]*G[n,f] + c[f]
// FUSED: one fp16 GEMM kernel computes u (104 fc cols/block) AND sx (10 sel
// cols, redundantly per block) and writes out directly. No U scratch, no epi.
// r14 fix: epilogue loops FULLY UNROLLED -> all acc[] indices static -> no
// local-memory demotion of the accumulator array (r14's 255-reg spill).
// ---------------------------------------------------------------------------

#define KDIM    4096
#define NFC     410
#define NCOLS   420
#define NBT     448
#define MMAX    4096

#define BM 128
#define BN 128
#define BK 64                        // fp16 elems -> 128 bytes per smem row
#define NKT (KDIM / BK)              // 64
#define STAGES 4
#define TILE_A  (BM * BK * 2)        // 16384
#define TILE_B  (BN * BK * 2)        // 16384
#define STAGE_BYTES (TILE_A + TILE_B) // 32768

#define KSPLIT 8
#define PREPW  4576

__device__ float  g_G[10 * 416];
__device__ float  g_c[416];
__device__ float  g_part[KSPLIT][PREPW];
__device__ __half g_Bt[NBT * KDIM];    // fp16 B (Wfc | Wsel | 0-pad)
__device__ __half g_xh[MMAX * KDIM];   // fp16 X

// ---------------- helpers ----------------------------------------------------
__device__ __forceinline__ uint32_t smem_u32(const void* p) {
    uint32_t a;
    asm("{ .reg .u64 t; cvta.to.shared.u64 t, %1; cvt.u32.u64 %0, t; }" : "=r"(a) : "l"(p));
    return a;
}
__device__ __forceinline__ void cp16(uint32_t dst, const void* src) {
    asm volatile("cp.async.cg.shared.global [%0], [%1], 16;"
                 :: "r"(dst), "l"(src) : "memory");
}
__device__ __forceinline__ void cp_commit() {
    asm volatile("cp.async.commit_group;" ::: "memory");
}
__device__ __forceinline__ void cp_wait2() {
    asm volatile("cp.async.wait_group 2;" ::: "memory");
}
__device__ __forceinline__ void ldsm4(uint32_t* r, uint32_t a) {
    asm volatile("ldmatrix.sync.aligned.m8n8.x4.shared.b16 {%0,%1,%2,%3}, [%4];"
                 : "=r"(r[0]), "=r"(r[1]), "=r"(r[2]), "=r"(r[3]) : "r"(a));
}
__device__ __forceinline__ void mma16(float* c, const uint32_t* a, const uint32_t* b) {
    asm volatile(
        "mma.sync.aligned.m16n8k16.row.col.f32.f16.f16.f32 "
        "{%0,%1,%2,%3}, {%4,%5,%6,%7}, {%8,%9}, {%0,%1,%2,%3};"
        : "+f"(c[0]), "+f"(c[1]), "+f"(c[2]), "+f"(c[3])
        : "r"(a[0]), "r"(a[1]), "r"(a[2]), "r"(a[3]), "r"(b[0]), "r"(b[1]));
}

// ---------------------------------------------------------------------------
// x -> fp16 (8 elems/thread, vectorized)
// ---------------------------------------------------------------------------
__global__ void xh_kernel(const float* __restrict__ x) {
    int i = (blockIdx.x * 256 + threadIdx.x) * 8;
    float4 v0 = *reinterpret_cast<const float4*>(x + i);
    float4 v1 = *reinterpret_cast<const float4*>(x + i + 4);
    __half2 h0 = __floats2half2_rn(v0.x, v0.y);
    __half2 h1 = __floats2half2_rn(v0.z, v0.w);
    __half2 h2 = __floats2half2_rn(v1.x, v1.y);
    __half2 h3 = __floats2half2_rn(v1.z, v1.w);
    uint4 pk;
    pk.x = *reinterpret_cast<uint32_t*>(&h0);
    pk.y = *reinterpret_cast<uint32_t*>(&h1);
    pk.z = *reinterpret_cast<uint32_t*>(&h2);
    pk.w = *reinterpret_cast<uint32_t*>(&h3);
    *reinterpret_cast<uint4*>(g_xh + i) = pk;
}

// ---------------------------------------------------------------------------
// prep pass 1: G/c partials (f<410) + fp16 B materialization (all f<448)
// ---------------------------------------------------------------------------
__global__ void prep_part(const float* __restrict__ Wfc, const float* __restrict__ Wsel,
                          const float* __restrict__ Wexp, const float* __restrict__ bexp) {
    int f  = blockIdx.x;                 // 0..447
    int kz = blockIdx.y;
    int k0 = kz * 512;
    const float* src = nullptr;
    if (f < NFC)        src = Wfc + (size_t)f * KDIM + k0;
    else if (f < NCOLS) src = Wsel + (size_t)(f - NFC) * KDIM + k0;

    float acc[11];
#pragma unroll
    for (int v = 0; v < 11; v++) acc[v] = 0.f;

#pragma unroll
    for (int it = 0; it < 4; it++) {
        int k = it * 128 + threadIdx.x;
        float w = src ? src[k] : 0.f;
        g_Bt[(size_t)f * KDIM + k0 + k] = __float2half_rn(w);
        if (f < NFC) {
            const float* we = Wexp + (size_t)(k0 + k) * 10;
#pragma unroll
            for (int n = 0; n < 10; n++) acc[n] += w * we[n];
            acc[10] += w * bexp[k0 + k];
        }
    }
    if (f >= NFC) return;

    __shared__ float red[4][11];
    int lane = threadIdx.x & 31, warp = threadIdx.x >> 5;
#pragma unroll
    for (int v = 0; v < 11; v++) {
        float s = acc[v];
#pragma unroll
        for (int o = 16; o; o >>= 1) s += __shfl_xor_sync(0xffffffffu, s, o);
        if (lane == 0) red[warp][v] = s;
    }
    __syncthreads();
    if (threadIdx.x < 11) {
        float s = red[0][threadIdx.x] + red[1][threadIdx.x] +
                  red[2][threadIdx.x] + red[3][threadIdx.x];
        g_part[kz][threadIdx.x * 416 + f] = s;
    }
}

__global__ void prep_combine(const float* __restrict__ bfc) {
    int i = blockIdx.x * 256 + threadIdx.x;
    if (i >= PREPW) return;
    float s = 0.f;
#pragma unroll
    for (int kz = 0; kz < KSPLIT; kz++) s += g_part[kz][i];
    if (i < 10 * 416) {
        g_G[i] = s;
    } else {
        int f = i - 10 * 416;
        g_c[f] = (f < NFC) ? s + bfc[f] : s;
    }
}

// ---------------------------------------------------------------------------
// fused GEMM + epilogue: 128x128 block, 128 thr, 4 warps of 32x128
// ---------------------------------------------------------------------------
__global__ __launch_bounds__(128, 1)
void gemm_kernel(const float* __restrict__ bsel, float* __restrict__ out) {
    extern __shared__ char dyn[];
    char* bufs = (char*)(((uintptr_t)dyn + 1023) & ~(uintptr_t)1023);
    const uint32_t bufs_u32 = smem_u32(bufs);

    const int tid  = threadIdx.x;
    const int lane = tid & 31;
    const int warp = tid >> 5;         // wm 0..3 (rows), full 128 cols per warp
    const int m0   = blockIdx.y * BM;
    const int off_b = blockIdx.x * 104;   // fc column offset of this block

    // ---- loaders: lrow 0..15 (+16i slabs), 16B chunk lq ----
    const int lrow = tid >> 3;
    const int lq   = tid & 7;
    const uint32_t dstoff = (uint32_t)(lrow * 128 + ((lq * 16) ^ ((lrow & 7) << 4)));
    const char* aglob = (const char*)(g_xh + (size_t)(m0 + lrow) * KDIM) + lq * 16;

    // B row map: j<104 -> fc (pad if >=410); j in [104,114) -> sel; else pad
    const char* bptr[8];
#pragma unroll
    for (int i = 0; i < 8; i++) {
        int j = i * 16 + lrow;
        int q;
        if (j < 104) {
            q = off_b + j;
            if (q >= NFC) q = 424 + (q - NFC);      // zero pad rows
        } else if (j < 114) {
            q = NFC + (j - 104);                     // Wsel rows
        } else {
            q = 432 + (j - 114);                     // zero pad rows
        }
        bptr[i] = (const char*)(g_Bt + (size_t)q * KDIM) + lq * 16;
    }

    auto issue = [&](int kt) {
        int stage = kt & (STAGES - 1);
        uint32_t ad = bufs_u32 + stage * STAGE_BYTES + dstoff;
        uint32_t bd = ad + TILE_A;
        const char* as = aglob + (size_t)kt * 128;
#pragma unroll
        for (int i = 0; i < 8; i++)
            cp16(ad + i * 2048, as + (size_t)i * (16 * KDIM * 2));
#pragma unroll
        for (int i = 0; i < 8; i++)
            cp16(bd + i * 2048, bptr[i] + (size_t)kt * 128);
    };

    // ---- fragment constants (validated byte addressing) ----
    const uint32_t aoff = (uint32_t)((warp * 32 + (lane & 15)) * 128);
    const uint32_t xS   = (uint32_t)((lane & 7) << 4);
    const uint32_t hA   = (lane & 16) ? 16u : 0u;
    const uint32_t boff = (uint32_t)(((lane & 7) + ((lane & 16) ? 8 : 0)) * 128);
    const uint32_t hB   = (lane & 8) ? 16u : 0u;

    float acc[2][16][4];
#pragma unroll
    for (int mi = 0; mi < 2; mi++)
#pragma unroll
        for (int nj = 0; nj < 16; nj++)
#pragma unroll
            for (int q = 0; q < 4; q++) acc[mi][nj][q] = 0.f;

    issue(0); cp_commit();
    issue(1); cp_commit();
    issue(2); cp_commit();

#pragma unroll 1
    for (int kt = 0; kt < NKT; kt++) {
        cp_wait2();
        __syncthreads();
        if (kt + 3 < NKT) issue(kt + 3);
        cp_commit();

        const uint32_t As = bufs_u32 + (kt & (STAGES - 1)) * STAGE_BYTES;
        const uint32_t Bs = As + TILE_A;
#pragma unroll
        for (int ks = 0; ks < 4; ks++) {
            const uint32_t ka = (uint32_t)(ks * 32 + hA) ^ xS;
            const uint32_t kb = (uint32_t)(ks * 32 + hB) ^ xS;
            uint32_t a[2][4], b[8][4];
#pragma unroll
            for (int mi = 0; mi < 2; mi++) ldsm4(a[mi], As + aoff + mi * 2048 + ka);
#pragma unroll
            for (int p = 0; p < 8; p++)   ldsm4(b[p], Bs + boff + p * 2048 + kb);
#pragma unroll
            for (int mi = 0; mi < 2; mi++)
#pragma unroll
                for (int p = 0; p < 8; p++) {
                    mma16(acc[mi][2 * p],     a[mi], &b[p][0]);
                    mma16(acc[mi][2 * p + 1], a[mi], &b[p][2]);
                }
        }
    }

    // ================= fused epilogue (FULLY UNROLLED: static acc indices) ===
    const int gid = lane >> 2;
    const int tig = lane & 3;
    __syncthreads();                 // mainloop smem dead; reuse buffers

    float* sxbuf = reinterpret_cast<float*>(bufs);        // [128][12]
    float* Gs    = sxbuf + 128 * 12;                      // [10][104]
    float* cs    = Gs + 10 * 104;                         // [104]

    // write sx (sel cols 104..113 = nj 13 pair + nj 14 first pair) + bsel
#pragma unroll
    for (int mi = 0; mi < 2; mi++) {
        int r0 = warp * 32 + mi * 16 + gid;
        sxbuf[r0 * 12 + 2 * tig]           = acc[mi][13][0] + bsel[2 * tig];
        sxbuf[r0 * 12 + 2 * tig + 1]       = acc[mi][13][1] + bsel[2 * tig + 1];
        sxbuf[(r0 + 8) * 12 + 2 * tig]     = acc[mi][13][2] + bsel[2 * tig];
        sxbuf[(r0 + 8) * 12 + 2 * tig + 1] = acc[mi][13][3] + bsel[2 * tig + 1];
        if (tig == 0) {
            sxbuf[r0 * 12 + 8]       = acc[mi][14][0] + bsel[8];
            sxbuf[r0 * 12 + 9]       = acc[mi][14][1] + bsel[9];
            sxbuf[(r0 + 8) * 12 + 8] = acc[mi][14][2] + bsel[8];
            sxbuf[(r0 + 8) * 12 + 9] = acc[mi][14][3] + bsel[9];
        }
    }
    // stage G/c slab
#pragma unroll 1
    for (int n = 0; n < 10; n++)
        for (int j = tid; j < 104; j += 128) Gs[n * 104 + j] = g_G[n * 416 + off_b + j];
    for (int j = tid; j < 104; j += 128) cs[j] = g_c[off_b + j];
    __syncthreads();

    // stores: fc cols are nj 0..12 (col = nj*8 + 2*tig < 104). FULL unroll.
#pragma unroll
    for (int nj = 0; nj < 13; nj++) {
        int col = nj * 8 + 2 * tig;
        int f = off_b + col;
        if (f < NFC) {                               // block-3 pad tail guard
            float2 c2 = *reinterpret_cast<float2*>(cs + col);
#pragma unroll
            for (int mi = 0; mi < 2; mi++) {
                int r0 = warp * 32 + mi * 16 + gid;
                float* o0 = out + (size_t)(m0 + r0) * 4096;
                float* o1 = out + (size_t)(m0 + r0 + 8) * 4096;
                float u0x = acc[mi][nj][0] + c2.x, u0y = acc[mi][nj][1] + c2.y;
                float u1x = acc[mi][nj][2] + c2.x, u1y = acc[mi][nj][3] + c2.y;
#pragma unroll
                for (int n = 0; n < 10; n++) {
                    if (n == 9 && f >= 406) break;   // out truncated at 4096
                    float2 g2 = *reinterpret_cast<float2*>(Gs + n * 104 + col);
                    float s0 = sxbuf[r0 * 12 + n];
                    float s1 = sxbuf[(r0 + 8) * 12 + n];
                    float2 v0 = make_float2(fmaf(s0, g2.x, u0x), fmaf(s0, g2.y, u0y));
                    float2 v1 = make_float2(fmaf(s1, g2.x, u1x), fmaf(s1, g2.y, u1y));
                    *reinterpret_cast<float2*>(o0 + n * NFC + f) = v0;
                    *reinterpret_cast<float2*>(o1 + n * NFC + f) = v1;
                }
            }
        }
    }
}

// ---------------------------------------------------------------------------
extern "C" void kernel_launch(void* const* d_in, const int* in_sizes, int n_in,
                              void* d_out, int out_size) {
    const float* x    = (const float*)d_in[0];
    const float* Wsel = (const float*)d_in[1];
    const float* bsel = (const float*)d_in[2];
    const float* Wexp = (const float*)d_in[3];
    const float* bexp = (const float*)d_in[4];
    const float* Wfc  = (const float*)d_in[5];
    const float* bfc  = (const float*)d_in[6];
    float* out = (float*)d_out;

    int M = in_sizes[0] / KDIM;   // 4096

    const int smem_bytes = STAGES * STAGE_BYTES + 1024;   // 132096
    cudaFuncSetAttribute(gemm_kernel, cudaFuncAttributeMaxDynamicSharedMemorySize, smem_bytes);

    xh_kernel<<<(M * KDIM) / (256 * 8), 256>>>(x);
    prep_part<<<dim3(NBT, KSPLIT), 128>>>(Wfc, Wsel, Wexp, bexp);
    prep_combine<<<(PREPW + 255) / 256, 256>>>(bfc);
    dim3 grid(4, M / BM);   // 4 x 32 = 128 blocks
    gemm_kernel<<<grid, 128, smem_bytes>>>(bsel, out);
}

// round 16
// speedup vs baseline: 3.3930x; 1.1916x over previous
#include <cuda_runtime.h>
#include <cuda_fp16.h>
#include <cstdint>

// ---------------------------------------------------------------------------
// y[m, n*410+f] = u[m,f] + sx[m,n]*G[n,f] + c[f]
//   U[:, 0:410] = X @ Wfc^T + c,  U[:, 410:420] = X @ Wsel^T + bsel
//   G = Wfc @ Wexp, c = Wfc @ bexp + bfc
// r12 split design (validated 102.5us) + two shavings:
//  - prep_part: 8 f-rows/block, Wexp slice staged in smem (71MB -> 16MB traffic)
//  - c/bsel folded into the GEMM U-write; epi does fmaf(sx, g, u) only.
// GEMM: mma.sync m16n8k16 fp16, 128 thr, 4 warps of 32x112, BN=112,
// cp.async 4-stage ring, zero in-loop cvt (A/B pre-converted fp16).
// ---------------------------------------------------------------------------

#define KDIM    4096
#define NFC     410
#define NCOLS   420
#define NBT     448
#define USTRIDE 432
#define MMAX    4096

#define BM 128
#define BN 112
#define BK 64                        // fp16 elems -> 128 bytes per smem row
#define NKT (KDIM / BK)              // 64
#define STAGES 4
#define TILE_A  (BM * BK * 2)        // 16384
#define TILE_B  (BN * BK * 2)        // 14336
#define STAGE_BYTES (TILE_A + TILE_B) // 30720

#define KSPLIT 8
#define PREPW  4576

__device__ float  g_U[MMAX * USTRIDE];
__device__ float  g_G[10 * 416];
__device__ float  g_c[416];
__device__ float  g_part[KSPLIT][PREPW];
__device__ __half g_Bt[NBT * KDIM];    // fp16 B (Wfc | Wsel | 0-pad)
__device__ __half g_xh[MMAX * KDIM];   // fp16 X

// ---------------- helpers ----------------------------------------------------
__device__ __forceinline__ uint32_t smem_u32(const void* p) {
    uint32_t a;
    asm("{ .reg .u64 t; cvta.to.shared.u64 t, %1; cvt.u32.u64 %0, t; }" : "=r"(a) : "l"(p));
    return a;
}
__device__ __forceinline__ void cp16(uint32_t dst, const void* src) {
    asm volatile("cp.async.cg.shared.global [%0], [%1], 16;"
                 :: "r"(dst), "l"(src) : "memory");
}
__device__ __forceinline__ void cp_commit() {
    asm volatile("cp.async.commit_group;" ::: "memory");
}
__device__ __forceinline__ void cp_wait2() {
    asm volatile("cp.async.wait_group 2;" ::: "memory");
}
__device__ __forceinline__ void ldsm4(uint32_t* r, uint32_t a) {
    asm volatile("ldmatrix.sync.aligned.m8n8.x4.shared.b16 {%0,%1,%2,%3}, [%4];"
                 : "=r"(r[0]), "=r"(r[1]), "=r"(r[2]), "=r"(r[3]) : "r"(a));
}
__device__ __forceinline__ void ldsm2(uint32_t* r, uint32_t a) {
    asm volatile("ldmatrix.sync.aligned.m8n8.x2.shared.b16 {%0,%1}, [%2];"
                 : "=r"(r[0]), "=r"(r[1]) : "r"(a));
}
__device__ __forceinline__ void mma16(float* c, const uint32_t* a, const uint32_t* b) {
    asm volatile(
        "mma.sync.aligned.m16n8k16.row.col.f32.f16.f16.f32 "
        "{%0,%1,%2,%3}, {%4,%5,%6,%7}, {%8,%9}, {%0,%1,%2,%3};"
        : "+f"(c[0]), "+f"(c[1]), "+f"(c[2]), "+f"(c[3])
        : "r"(a[0]), "r"(a[1]), "r"(a[2]), "r"(a[3]), "r"(b[0]), "r"(b[1]));
}

// ---------------------------------------------------------------------------
// x -> fp16 (8 elems/thread, vectorized)
// ---------------------------------------------------------------------------
__global__ void xh_kernel(const float* __restrict__ x) {
    int i = (blockIdx.x * 256 + threadIdx.x) * 8;
    float4 v0 = *reinterpret_cast<const float4*>(x + i);
    float4 v1 = *reinterpret_cast<const float4*>(x + i + 4);
    __half2 h0 = __floats2half2_rn(v0.x, v0.y);
    __half2 h1 = __floats2half2_rn(v0.z, v0.w);
    __half2 h2 = __floats2half2_rn(v1.x, v1.y);
    __half2 h3 = __floats2half2_rn(v1.z, v1.w);
    uint4 pk;
    pk.x = *reinterpret_cast<uint32_t*>(&h0);
    pk.y = *reinterpret_cast<uint32_t*>(&h1);
    pk.z = *reinterpret_cast<uint32_t*>(&h2);
    pk.w = *reinterpret_cast<uint32_t*>(&h3);
    *reinterpret_cast<uint4*>(g_xh + i) = pk;
}

// ---------------------------------------------------------------------------
// prep pass 1: 8 f-rows per block (warp-per-f), Wexp slice staged in smem.
// grid (56, 8), 256 threads. Writes g_Bt (fp16, 0-pad) + g_part partials.
// ---------------------------------------------------------------------------
__global__ void prep_part(const float* __restrict__ Wfc, const float* __restrict__ Wsel,
                          const float* __restrict__ Wexp, const float* __restrict__ bexp) {
    __shared__ float swe[512 * 10];
    __shared__ float sbe[512];
    const int kz = blockIdx.y;
    const int k0 = kz * 512;
    const int lane = threadIdx.x & 31;
    const int warp = threadIdx.x >> 5;
    const int f = blockIdx.x * 8 + warp;     // 0..447

    for (int i = threadIdx.x; i < 5120; i += 256) swe[i] = Wexp[(size_t)k0 * 10 + i];
    for (int i = threadIdx.x; i < 512; i += 256)  sbe[i] = bexp[k0 + i];
    __syncthreads();

    const float* src = nullptr;
    if (f < NFC)        src = Wfc + (size_t)f * KDIM + k0;
    else if (f < NCOLS) src = Wsel + (size_t)(f - NFC) * KDIM + k0;

    float acc[11];
#pragma unroll
    for (int v = 0; v < 11; v++) acc[v] = 0.f;

#pragma unroll
    for (int it = 0; it < 16; it++) {
        int k = it * 32 + lane;
        float w = src ? src[k] : 0.f;
        g_Bt[(size_t)f * KDIM + k0 + k] = __float2half_rn(w);
        if (f < NFC) {
#pragma unroll
            for (int n = 0; n < 10; n++) acc[n] += w * swe[k * 10 + n];
            acc[10] += w * sbe[k];
        }
    }
    if (f >= NFC) return;

#pragma unroll
    for (int v = 0; v < 11; v++) {
#pragma unroll
        for (int o = 16; o; o >>= 1) acc[v] += __shfl_xor_sync(0xffffffffu, acc[v], o);
    }
    if (lane == 0) {
#pragma unroll
        for (int v = 0; v < 11; v++) g_part[kz][v * 416 + f] = acc[v];
    }
}

__global__ void prep_combine(const float* __restrict__ bfc) {
    int i = blockIdx.x * 256 + threadIdx.x;
    if (i >= PREPW) return;
    float s = 0.f;
#pragma unroll
    for (int kz = 0; kz < KSPLIT; kz++) s += g_part[kz][i];
    if (i < 10 * 416) {
        g_G[i] = s;
    } else {
        int f = i - 10 * 416;
        g_c[f] = (f < NFC) ? s + bfc[f] : s;
    }
}

// ---------------------------------------------------------------------------
// GEMM: 128x112 block, 4 warps (4wm x 1wn) of 32x112, fp16 m16n8k16.
// U-write adds c[col] (fc cols) or bsel[col-410] (sel cols).
// ---------------------------------------------------------------------------
__global__ __launch_bounds__(128, 1)
void gemm_kernel(const float* __restrict__ bsel) {
    extern __shared__ char dyn[];
    char* bufs = (char*)(((uintptr_t)dyn + 1023) & ~(uintptr_t)1023);
    const uint32_t bufs_u32 = smem_u32(bufs);

    const int tid  = threadIdx.x;
    const int lane = tid & 31;
    const int warp = tid >> 5;         // wm 0..3, single wn
    const int m0   = blockIdx.y * BM;
    const int n0   = blockIdx.x * BN;

    // ---- loader: lrow 0..15 (+16i slabs), 16B chunk lq ----
    const int lrow = tid >> 3;
    const int lq   = tid & 7;
    const uint32_t dstoff = (uint32_t)(lrow * 128 + ((lq * 16) ^ ((lrow & 7) << 4)));
    const char* aglob = (const char*)(g_xh + (size_t)(m0 + lrow) * KDIM) + lq * 16;
    const char* bglob = (const char*)(g_Bt + (size_t)(n0 + lrow) * KDIM) + lq * 16;

    auto issue = [&](int kt) {
        int stage = kt & (STAGES - 1);
        uint32_t ad = bufs_u32 + stage * STAGE_BYTES + dstoff;
        uint32_t bd = ad + TILE_A;
        const char* as = aglob + (size_t)kt * 128;
        const char* bs = bglob + (size_t)kt * 128;
#pragma unroll
        for (int i = 0; i < 8; i++)
            cp16(ad + i * 2048, as + (size_t)i * (16 * KDIM * 2));
#pragma unroll
        for (int i = 0; i < 7; i++)
            cp16(bd + i * 2048, bs + (size_t)i * (16 * KDIM * 2));
    };

    // ---- fragment constants (validated byte addressing) ----
    const uint32_t aoff = (uint32_t)((warp * 32 + (lane & 15)) * 128);
    const uint32_t xS   = (uint32_t)((lane & 7) << 4);
    const uint32_t hA   = (lane & 16) ? 16u : 0u;
    const uint32_t boff = (uint32_t)(((lane & 7) + ((lane & 16) ? 8 : 0)) * 128);
    const uint32_t hB   = (lane & 8) ? 16u : 0u;

    float acc[2][14][4];
#pragma unroll
    for (int mi = 0; mi < 2; mi++)
#pragma unroll
        for (int nj = 0; nj < 14; nj++)
#pragma unroll
            for (int q = 0; q < 4; q++) acc[mi][nj][q] = 0.f;

    issue(0); cp_commit();
    issue(1); cp_commit();
    issue(2); cp_commit();

    uint32_t a[2][2][4], b[2][7][4];   // double-buffered fp16x2 fragments

#pragma unroll 1
    for (int kt = 0; kt < NKT; kt++) {
        cp_wait2();
        __syncthreads();
        if (kt + 3 < NKT) issue(kt + 3);
        cp_commit();

        const uint32_t As = bufs_u32 + (kt & (STAGES - 1)) * STAGE_BYTES;
        const uint32_t Bs = As + TILE_A;

        // preload ks=0
        {
            const uint32_t ka = hA ^ xS;
            const uint32_t kb = hB ^ xS;
#pragma unroll
            for (int mi = 0; mi < 2; mi++) ldsm4(a[0][mi], As + aoff + mi * 2048 + ka);
#pragma unroll
            for (int p = 0; p < 7; p++)   ldsm4(b[0][p], Bs + boff + p * 2048 + kb);
        }

#pragma unroll
        for (int ks = 0; ks < 4; ks++) {
            const int cur = ks & 1;
            const int nxt = cur ^ 1;
            if (ks < 3) {
                const uint32_t ka = (uint32_t)((ks + 1) * 32 + hA) ^ xS;
                const uint32_t kb = (uint32_t)((ks + 1) * 32 + hB) ^ xS;
#pragma unroll
                for (int mi = 0; mi < 2; mi++) ldsm4(a[nxt][mi], As + aoff + mi * 2048 + ka);
#pragma unroll
                for (int p = 0; p < 7; p++)   ldsm4(b[nxt][p], Bs + boff + p * 2048 + kb);
            }
#pragma unroll
            for (int mi = 0; mi < 2; mi++)
#pragma unroll
                for (int p = 0; p < 7; p++) {
                    mma16(acc[mi][2 * p],     a[cur][mi], &b[cur][p][0]);
                    mma16(acc[mi][2 * p + 1], a[cur][mi], &b[cur][p][2]);
                }
        }
    }

    // ---- write U + c/bsel (guard pad columns) ----
    const int gid = lane >> 2;
    const int tig = lane & 3;
#pragma unroll
    for (int mi = 0; mi < 2; mi++) {
        int r0 = m0 + warp * 32 + mi * 16 + gid;
#pragma unroll
        for (int nj = 0; nj < 14; nj++) {
            int col = n0 + nj * 8 + 2 * tig;
            if (col < NCOLS) {
                float2 add;
                if (col < NFC) add = *reinterpret_cast<const float2*>(&g_c[col]);
                else           add = *reinterpret_cast<const float2*>(&bsel[col - NFC]);
                *reinterpret_cast<float2*>(&g_U[(size_t)r0 * USTRIDE + col]) =
                    make_float2(acc[mi][nj][0] + add.x, acc[mi][nj][1] + add.y);
                *reinterpret_cast<float2*>(&g_U[(size_t)(r0 + 8) * USTRIDE + col]) =
                    make_float2(acc[mi][nj][2] + add.x, acc[mi][nj][3] + add.y);
            }
        }
    }
}

// ---------------------------------------------------------------------------
// epilogue: float2, 1 row/block; u already has c, sx already has bsel
// ---------------------------------------------------------------------------
__global__ void epi_kernel(float* __restrict__ out) {
    int m = blockIdx.x;
    __shared__ float sx[10];
    if (threadIdx.x < 10)
        sx[threadIdx.x] = g_U[(size_t)m * USTRIDE + NFC + threadIdx.x];
    __syncthreads();
    const float* Ur = g_U + (size_t)m * USTRIDE;
    float* orow = out + (size_t)m * 4096;
#pragma unroll 1
    for (int n = 0; n < 10; n++) {
        int base = n * NFC;
        float sxn = sx[n];
        int lim = (n == 9) ? (4096 - base) : NFC;
        const float* Gn = g_G + n * 416;
        for (int f = threadIdx.x * 2; f < lim; f += 512) {
            float2 u = *reinterpret_cast<const float2*>(Ur + f);
            float2 g = *reinterpret_cast<const float2*>(Gn + f);
            float2 r;
            r.x = fmaf(sxn, g.x, u.x);
            r.y = fmaf(sxn, g.y, u.y);
            *reinterpret_cast<float2*>(orow + base + f) = r;
        }
    }
}

// ---------------------------------------------------------------------------
extern "C" void kernel_launch(void* const* d_in, const int* in_sizes, int n_in,
                              void* d_out, int out_size) {
    const float* x    = (const float*)d_in[0];
    const float* Wsel = (const float*)d_in[1];
    const float* bsel = (const float*)d_in[2];
    const float* Wexp = (const float*)d_in[3];
    const float* bexp = (const float*)d_in[4];
    const float* Wfc  = (const float*)d_in[5];
    const float* bfc  = (const float*)d_in[6];
    float* out = (float*)d_out;

    int M = in_sizes[0] / KDIM;   // 4096

    const int smem_bytes = STAGES * STAGE_BYTES + 1024;   // 123904
    cudaFuncSetAttribute(gemm_kernel, cudaFuncAttributeMaxDynamicSharedMemorySize, smem_bytes);

    xh_kernel<<<(M * KDIM) / (256 * 8), 256>>>(x);
    prep_part<<<dim3(56, KSPLIT), 256>>>(Wfc, Wsel, Wexp, bexp);
    prep_combine<<<(PREPW + 255) / 256, 256>>>(bfc);
    dim3 grid(4, M / BM);   // 4 x 32 = 128 blocks
    gemm_kernel<<<grid, 128, smem_bytes>>>(bsel);
    epi_kernel<<<M, 256>>>(out);
}

// round 17
// speedup vs baseline: 3.6211x; 1.0672x over previous
#include <cuda_runtime.h>
#include <cuda_fp16.h>
#include <cstdint>

// ---------------------------------------------------------------------------
// y[m, n*410+f] = u[m,f] + sx[m,n]*G[n,f] + c[f]
//   U[:, 0:410] = X @ Wfc^T + c,  U[:, 410:420] = X @ Wsel^T + bsel
//   G = Wfc @ Wexp, c = Wfc @ bexp + bfc
// GEMM: mma.sync m16n8k16 fp16, 128 thr, 4 warps of 32x112, BN=112.
// NEW: 2 k-tiles per barrier (STAGES=6 ring, wait_group 2, double-commit)
//      -> half the __syncthreads; xh + prep_part merged into one kernel.
// ---------------------------------------------------------------------------

#define KDIM    4096
#define NFC     410
#define NCOLS   420
#define NBT     448
#define USTRIDE 432
#define MMAX    4096

#define BM 128
#define BN 112
#define BK 64                        // fp16 elems -> 128 bytes per smem row
#define NKT (KDIM / BK)              // 64
#define STAGES 6
#define TILE_A  (BM * BK * 2)        // 16384
#define TILE_B  (BN * BK * 2)        // 14336
#define STAGE_BYTES (TILE_A + TILE_B) // 30720

#define KSPLIT 8
#define PREPW  4576
#define XH_BLOCKS ((MMAX * KDIM) / (256 * 8))   // 8192

__device__ float  g_U[MMAX * USTRIDE];
__device__ float  g_G[10 * 416];
__device__ float  g_c[416];
__device__ float  g_part[KSPLIT][PREPW];
__device__ __half g_Bt[NBT * KDIM];    // fp16 B (Wfc | Wsel | 0-pad)
__device__ __half g_xh[MMAX * KDIM];   // fp16 X

// ---------------- helpers ----------------------------------------------------
__device__ __forceinline__ uint32_t smem_u32(const void* p) {
    uint32_t a;
    asm("{ .reg .u64 t; cvta.to.shared.u64 t, %1; cvt.u32.u64 %0, t; }" : "=r"(a) : "l"(p));
    return a;
}
__device__ __forceinline__ void cp16(uint32_t dst, const void* src) {
    asm volatile("cp.async.cg.shared.global [%0], [%1], 16;"
                 :: "r"(dst), "l"(src) : "memory");
}
__device__ __forceinline__ void cp_commit() {
    asm volatile("cp.async.commit_group;" ::: "memory");
}
__device__ __forceinline__ void cp_wait2() {
    asm volatile("cp.async.wait_group 2;" ::: "memory");
}
__device__ __forceinline__ void ldsm4(uint32_t* r, uint32_t a) {
    asm volatile("ldmatrix.sync.aligned.m8n8.x4.shared.b16 {%0,%1,%2,%3}, [%4];"
                 : "=r"(r[0]), "=r"(r[1]), "=r"(r[2]), "=r"(r[3]) : "r"(a));
}
__device__ __forceinline__ void mma16(float* c, const uint32_t* a, const uint32_t* b) {
    asm volatile(
        "mma.sync.aligned.m16n8k16.row.col.f32.f16.f16.f32 "
        "{%0,%1,%2,%3}, {%4,%5,%6,%7}, {%8,%9}, {%0,%1,%2,%3};"
        : "+f"(c[0]), "+f"(c[1]), "+f"(c[2]), "+f"(c[3])
        : "r"(a[0]), "r"(a[1]), "r"(a[2]), "r"(a[3]), "r"(b[0]), "r"(b[1]));
}

// ---------------------------------------------------------------------------
// front kernel: blocks [0, XH_BLOCKS) do x->fp16; rest do prep_part work
// ---------------------------------------------------------------------------
__global__ void front_kernel(const float* __restrict__ x,
                             const float* __restrict__ Wfc, const float* __restrict__ Wsel,
                             const float* __restrict__ Wexp, const float* __restrict__ bexp) {
    __shared__ float swe[512 * 10];
    __shared__ float sbe[512];

    if (blockIdx.x < XH_BLOCKS) {
        int i = (blockIdx.x * 256 + threadIdx.x) * 8;
        float4 v0 = *reinterpret_cast<const float4*>(x + i);
        float4 v1 = *reinterpret_cast<const float4*>(x + i + 4);
        __half2 h0 = __floats2half2_rn(v0.x, v0.y);
        __half2 h1 = __floats2half2_rn(v0.z, v0.w);
        __half2 h2 = __floats2half2_rn(v1.x, v1.y);
        __half2 h3 = __floats2half2_rn(v1.z, v1.w);
        uint4 pk;
        pk.x = *reinterpret_cast<uint32_t*>(&h0);
        pk.y = *reinterpret_cast<uint32_t*>(&h1);
        pk.z = *reinterpret_cast<uint32_t*>(&h2);
        pk.w = *reinterpret_cast<uint32_t*>(&h3);
        *reinterpret_cast<uint4*>(g_xh + i) = pk;
        return;
    }

    // prep_part: 8 f-rows per block (warp-per-f), Wexp slice staged in smem
    int pb = blockIdx.x - XH_BLOCKS;       // 0..447
    const int fx = pb % 56;
    const int kz = pb / 56;                // 0..7
    const int k0 = kz * 512;
    const int lane = threadIdx.x & 31;
    const int warp = threadIdx.x >> 5;
    const int f = fx * 8 + warp;           // 0..447

    for (int i = threadIdx.x; i < 5120; i += 256) swe[i] = Wexp[(size_t)k0 * 10 + i];
    for (int i = threadIdx.x; i < 512; i += 256)  sbe[i] = bexp[k0 + i];
    __syncthreads();

    const float* src = nullptr;
    if (f < NFC)        src = Wfc + (size_t)f * KDIM + k0;
    else if (f < NCOLS) src = Wsel + (size_t)(f - NFC) * KDIM + k0;

    float acc[11];
#pragma unroll
    for (int v = 0; v < 11; v++) acc[v] = 0.f;

#pragma unroll
    for (int it = 0; it < 16; it++) {
        int k = it * 32 + lane;
        float w = src ? src[k] : 0.f;
        g_Bt[(size_t)f * KDIM + k0 + k] = __float2half_rn(w);
        if (f < NFC) {
#pragma unroll
            for (int n = 0; n < 10; n++) acc[n] += w * swe[k * 10 + n];
            acc[10] += w * sbe[k];
        }
    }
    if (f >= NFC) return;

#pragma unroll
    for (int v = 0; v < 11; v++) {
#pragma unroll
        for (int o = 16; o; o >>= 1) acc[v] += __shfl_xor_sync(0xffffffffu, acc[v], o);
    }
    if (lane == 0) {
#pragma unroll
        for (int v = 0; v < 11; v++) g_part[kz][v * 416 + f] = acc[v];
    }
}

__global__ void prep_combine(const float* __restrict__ bfc) {
    int i = blockIdx.x * 256 + threadIdx.x;
    if (i >= PREPW) return;
    float s = 0.f;
#pragma unroll
    for (int kz = 0; kz < KSPLIT; kz++) s += g_part[kz][i];
    if (i < 10 * 416) {
        g_G[i] = s;
    } else {
        int f = i - 10 * 416;
        g_c[f] = (f < NFC) ? s + bfc[f] : s;
    }
}

// ---------------------------------------------------------------------------
// GEMM: 128x112 block, 4 warps (4wm x 1wn) of 32x112, fp16 m16n8k16.
// 2 k-tiles per barrier; STAGES=6 ring. U-write adds c/bsel.
// ---------------------------------------------------------------------------
__global__ __launch_bounds__(128, 1)
void gemm_kernel(const float* __restrict__ bsel) {
    extern __shared__ char dyn[];
    char* bufs = (char*)(((uintptr_t)dyn + 1023) & ~(uintptr_t)1023);
    const uint32_t bufs_u32 = smem_u32(bufs);

    const int tid  = threadIdx.x;
    const int lane = tid & 31;
    const int warp = tid >> 5;         // wm 0..3, single wn
    const int m0   = blockIdx.y * BM;
    const int n0   = blockIdx.x * BN;

    // ---- loader: lrow 0..15 (+16i slabs), 16B chunk lq ----
    const int lrow = tid >> 3;
    const int lq   = tid & 7;
    const uint32_t dstoff = (uint32_t)(lrow * 128 + ((lq * 16) ^ ((lrow & 7) << 4)));
    const char* aglob = (const char*)(g_xh + (size_t)(m0 + lrow) * KDIM) + lq * 16;
    const char* bglob = (const char*)(g_Bt + (size_t)(n0 + lrow) * KDIM) + lq * 16;

    auto issue = [&](int kt) {
        int stage = kt % STAGES;
        uint32_t ad = bufs_u32 + stage * STAGE_BYTES + dstoff;
        uint32_t bd = ad + TILE_A;
        const char* as = aglob + (size_t)kt * 128;
        const char* bs = bglob + (size_t)kt * 128;
#pragma unroll
        for (int i = 0; i < 8; i++)
            cp16(ad + i * 2048, as + (size_t)i * (16 * KDIM * 2));
#pragma unroll
        for (int i = 0; i < 7; i++)
            cp16(bd + i * 2048, bs + (size_t)i * (16 * KDIM * 2));
    };

    // ---- fragment constants (validated byte addressing) ----
    const uint32_t aoff = (uint32_t)((warp * 32 + (lane & 15)) * 128);
    const uint32_t xS   = (uint32_t)((lane & 7) << 4);
    const uint32_t hA   = (lane & 16) ? 16u : 0u;
    const uint32_t boff = (uint32_t)(((lane & 7) + ((lane & 16) ? 8 : 0)) * 128);
    const uint32_t hB   = (lane & 8) ? 16u : 0u;

    float acc[2][14][4];
#pragma unroll
    for (int mi = 0; mi < 2; mi++)
#pragma unroll
        for (int nj = 0; nj < 14; nj++)
#pragma unroll
            for (int q = 0; q < 4; q++) acc[mi][nj][q] = 0.f;

    issue(0); cp_commit();
    issue(1); cp_commit();
    issue(2); cp_commit();
    issue(3); cp_commit();

    uint32_t a[2][2][4], b[2][7][4];   // double-buffered fp16x2 fragments

    // process one k-tile from smem stage base (ks-pipelined fragments)
    auto compute_tile = [&](uint32_t As) {
        const uint32_t Bs = As + TILE_A;
        {
            const uint32_t ka = hA ^ xS;
            const uint32_t kb = hB ^ xS;
#pragma unroll
            for (int mi = 0; mi < 2; mi++) ldsm4(a[0][mi], As + aoff + mi * 2048 + ka);
#pragma unroll
            for (int p = 0; p < 7; p++)   ldsm4(b[0][p], Bs + boff + p * 2048 + kb);
        }
#pragma unroll
        for (int ks = 0; ks < 4; ks++) {
            const int cur = ks & 1;
            const int nxt = cur ^ 1;
            if (ks < 3) {
                const uint32_t ka = (uint32_t)((ks + 1) * 32 + hA) ^ xS;
                const uint32_t kb = (uint32_t)((ks + 1) * 32 + hB) ^ xS;
#pragma unroll
                for (int mi = 0; mi < 2; mi++) ldsm4(a[nxt][mi], As + aoff + mi * 2048 + ka);
#pragma unroll
                for (int p = 0; p < 7; p++)   ldsm4(b[nxt][p], Bs + boff + p * 2048 + kb);
            }
#pragma unroll
            for (int mi = 0; mi < 2; mi++)
#pragma unroll
                for (int p = 0; p < 7; p++) {
                    mma16(acc[mi][2 * p],     a[cur][mi], &b[cur][p][0]);
                    mma16(acc[mi][2 * p + 1], a[cur][mi], &b[cur][p][2]);
                }
        }
    };

#pragma unroll 1
    for (int kt = 0; kt < NKT; kt += 2) {
        cp_wait2();                 // stages kt, kt+1 complete (2 newest pend)
        __syncthreads();
        if (kt + 4 < NKT) issue(kt + 4);
        cp_commit();
        if (kt + 5 < NKT) issue(kt + 5);
        cp_commit();

        compute_tile(bufs_u32 + (kt % STAGES) * STAGE_BYTES);
        compute_tile(bufs_u32 + ((kt + 1) % STAGES) * STAGE_BYTES);
    }

    // ---- write U + c/bsel (guard pad columns) ----
    const int gid = lane >> 2;
    const int tig = lane & 3;
#pragma unroll
    for (int mi = 0; mi < 2; mi++) {
        int r0 = m0 + warp * 32 + mi * 16 + gid;
#pragma unroll
        for (int nj = 0; nj < 14; nj++) {
            int col = n0 + nj * 8 + 2 * tig;
            if (col < NCOLS) {
                float2 add;
                if (col < NFC) add = *reinterpret_cast<const float2*>(&g_c[col]);
                else           add = *reinterpret_cast<const float2*>(&bsel[col - NFC]);
                *reinterpret_cast<float2*>(&g_U[(size_t)r0 * USTRIDE + col]) =
                    make_float2(acc[mi][nj][0] + add.x, acc[mi][nj][1] + add.y);
                *reinterpret_cast<float2*>(&g_U[(size_t)(r0 + 8) * USTRIDE + col]) =
                    make_float2(acc[mi][nj][2] + add.x, acc[mi][nj][3] + add.y);
            }
        }
    }
}

// ---------------------------------------------------------------------------
// epilogue: float2, 1 row/block; u already has c, sx already has bsel
// ---------------------------------------------------------------------------
__global__ void epi_kernel(float* __restrict__ out) {
    int m = blockIdx.x;
    __shared__ float sx[10];
    if (threadIdx.x < 10)
        sx[threadIdx.x] = g_U[(size_t)m * USTRIDE + NFC + threadIdx.x];
    __syncthreads();
    const float* Ur = g_U + (size_t)m * USTRIDE;
    float* orow = out + (size_t)m * 4096;
#pragma unroll 1
    for (int n = 0; n < 10; n++) {
        int base = n * NFC;
        float sxn = sx[n];
        int lim = (n == 9) ? (4096 - base) : NFC;
        const float* Gn = g_G + n * 416;
        for (int f = threadIdx.x * 2; f < lim; f += 512) {
            float2 u = *reinterpret_cast<const float2*>(Ur + f);
            float2 g = *reinterpret_cast<const float2*>(Gn + f);
            float2 r;
            r.x = fmaf(sxn, g.x, u.x);
            r.y = fmaf(sxn, g.y, u.y);
            *reinterpret_cast<float2*>(orow + base + f) = r;
        }
    }
}

// ---------------------------------------------------------------------------
extern "C" void kernel_launch(void* const* d_in, const int* in_sizes, int n_in,
                              void* d_out, int out_size) {
    const float* x    = (const float*)d_in[0];
    const float* Wsel = (const float*)d_in[1];
    const float* bsel = (const float*)d_in[2];
    const float* Wexp = (const float*)d_in[3];
    const float* bexp = (const float*)d_in[4];
    const float* Wfc  = (const float*)d_in[5];
    const float* bfc  = (const float*)d_in[6];
    float* out = (float*)d_out;

    int M = in_sizes[0] / KDIM;   // 4096

    const int smem_bytes = STAGES * STAGE_BYTES + 1024;   // 185344
    cudaFuncSetAttribute(gemm_kernel, cudaFuncAttributeMaxDynamicSharedMemorySize, smem_bytes);

    front_kernel<<<XH_BLOCKS + 448, 256>>>(x, Wfc, Wsel, Wexp, bexp);
    prep_combine<<<(PREPW + 255) / 256, 256>>>(bfc);
    dim3 grid(4, M / BM);   // 4 x 32 = 128 blocks
    gemm_kernel<<<grid, 128, smem_bytes>>>(bsel);
    epi_kernel<<<M, 256>>>(out);
}